// round 12
// baseline (speedup 1.0000x reference)
#include <cuda_runtime.h>
#include <cuda_fp16.h>

#define IN_CH 65
#define HID   64
#define NPAIR 33   // ceil(65/2) packed k-pairs
#define MAX_NODES 100000
#define CAP      128   // bucket capacity per node (deg ~ Poisson(32))

typedef unsigned long long ull;

// ---------------------------------------------------------------------------
// Static scratch (no device-memory allocations allowed).
// g_cursor relies on zero-init for the first call; aggregate_kernel re-zeroes
// it on every execution (replay-safe invariant).
// ---------------------------------------------------------------------------
__device__ __align__(16) __half g_yh[(size_t)MAX_NODES * HID];  // y in fp16
__device__ int  g_cursor[MAX_NODES];                            // bucket fill counts
__device__ int2 g_entries[(size_t)MAX_NODES * CAP];             // (src, bits(w)) buckets

// ---------------------------------------------------------------------------
// Packed f32x2 helpers (Blackwell FFMA2 — only reachable via PTX)
// ---------------------------------------------------------------------------
__device__ __forceinline__ ull pack_f32x2(float lo, float hi) {
    ull r;
    asm("mov.b64 %0, {%1, %2};" : "=l"(r) : "f"(lo), "f"(hi));
    return r;
}
__device__ __forceinline__ void unpack_f32x2(ull v, float& lo, float& hi) {
    asm("mov.b64 {%0, %1}, %2;" : "=f"(lo), "=f"(hi) : "l"(v));
}
__device__ __forceinline__ void fma_f32x2(ull& d, ull a, ull b) {
    asm("fma.rn.f32x2 %0, %1, %2, %0;" : "+l"(d) : "l"(a), "l"(b));
}

// ---------------------------------------------------------------------------
// Kernel: per-node dual matvec. Same structure as the validated R9 kernel
// (4 nodes/iter, double-buffered smem x, register prefetch) but the W_root
// weights live in SMEM (conflict-free per-lane reads, reused across the 4
// nodes) instead of registers: ~66 fewer regs -> ~2x occupancy.
//   g_yh[n] = half(W_rel @ x[n]);  out[n] = W_root @ x[n] + b_rel
// ---------------------------------------------------------------------------
__global__ __launch_bounds__(64, 8) void transform_kernel(
    const float* __restrict__ x,
    const float* __restrict__ W_rel,
    const float* __restrict__ b_rel,
    const float* __restrict__ W_root,
    float* __restrict__ out,
    int n_nodes)
{
    const int o = threadIdx.x;  // 0..63 output channel

    // W_rel weights in registers (packed pairs).
    ull wrp[NPAIR];
    // W_root weights in smem: wop_s[p][o] (8B/lane, conflict-free).
    __shared__ ull wop_s[NPAIR][64];
#pragma unroll
    for (int p = 0; p < NPAIR; ++p) {
        const int k0 = 2 * p, k1 = 2 * p + 1;
        const float r0 = W_rel[o * IN_CH + k0];
        const float r1 = (k1 < IN_CH) ? W_rel[o * IN_CH + k1] : 0.0f;
        const float o0 = W_root[o * IN_CH + k0];
        const float o1 = (k1 < IN_CH) ? W_root[o * IN_CH + k1] : 0.0f;
        wrp[p] = pack_f32x2(r0, r1);
        wop_s[p][o] = pack_f32x2(o0, o1);
    }
    const float bias = b_rel[o];

    // Double-buffered x rows: 2 buffers x 4 nodes x 68 floats (16B-aligned).
    __shared__ __align__(16) float sx[2][4][68];
    if (o < 24) {
        const int b = o / 12, nd = (o % 12) / 3, k = 65 + (o % 3);
        sx[b][nd][k] = 0.0f;
    }

    const int total_elems = n_nodes * IN_CH;
    const int stride = gridDim.x * 4;

    int n0 = blockIdx.x * 4;

    // Stage iteration 0 into buffer 0.
    {
        const int base = n0 * IN_CH;
#pragma unroll
        for (int j = 0; j < 5; ++j) {
            const int idx = o + j * 64;
            if (idx < 4 * IN_CH && base + idx < total_elems) {
                const int nd = idx / IN_CH;
                const int k  = idx - nd * IN_CH;
                sx[0][nd][k] = x[base + idx];
            }
        }
    }
    __syncthreads();   // covers wop_s + sx buffer 0

    for (int it = 0; n0 < n_nodes; n0 += stride, ++it) {
        const int buf = it & 1;

        // Prefetch next iteration's rows into registers.
        const int nn = n0 + stride;
        float pf[5];
#pragma unroll
        for (int j = 0; j < 5; ++j) {
            const int idx = o + j * 64;
            const int gidx = nn * IN_CH + idx;
            pf[j] = (idx < 4 * IN_CH && nn < n_nodes && gidx < total_elems)
                        ? x[gidx] : 0.0f;
        }

        // Compute 4 nodes x 2 matrices = 8 independent packed chains.
        const ull* sp0 = reinterpret_cast<const ull*>(sx[buf][0]);
        const ull* sp1 = reinterpret_cast<const ull*>(sx[buf][1]);
        const ull* sp2 = reinterpret_cast<const ull*>(sx[buf][2]);
        const ull* sp3 = reinterpret_cast<const ull*>(sx[buf][3]);

        ull aY0 = 0, aY1 = 0, aY2 = 0, aY3 = 0;
        ull aO0 = 0, aO1 = 0, aO2 = 0, aO3 = 0;
#pragma unroll
        for (int p = 0; p < NPAIR; ++p) {
            const ull w_r = wrp[p];
            const ull w_o = wop_s[p][o];
            const ull x0 = sp0[p], x1 = sp1[p], x2 = sp2[p], x3 = sp3[p];
            fma_f32x2(aY0, w_r, x0); fma_f32x2(aO0, w_o, x0);
            fma_f32x2(aY1, w_r, x1); fma_f32x2(aO1, w_o, x1);
            fma_f32x2(aY2, w_r, x2); fma_f32x2(aO2, w_o, x2);
            fma_f32x2(aY3, w_r, x3); fma_f32x2(aO3, w_o, x3);
        }

        float lo, hi;
#define STORE_NODE(idx, AY, AO)                                              \
        if (n0 + (idx) < n_nodes) {                                         \
            unpack_f32x2(AY, lo, hi);                                       \
            g_yh[(size_t)(n0 + (idx)) * HID + o] = __float2half(lo + hi);   \
            unpack_f32x2(AO, lo, hi);                                       \
            out[(size_t)(n0 + (idx)) * HID + o] = lo + hi + bias;           \
        }
        STORE_NODE(0, aY0, aO0)
        STORE_NODE(1, aY1, aO1)
        STORE_NODE(2, aY2, aO2)
        STORE_NODE(3, aY3, aO3)
#undef STORE_NODE

        // Commit prefetched rows to the other buffer.
#pragma unroll
        for (int j = 0; j < 5; ++j) {
            const int idx = o + j * 64;
            if (idx < 4 * IN_CH) {
                const int nd = idx / IN_CH;
                const int k  = idx - nd * IN_CH;
                sx[buf ^ 1][nd][k] = pf[j];
            }
        }
        __syncthreads();
    }
}

// ---------------------------------------------------------------------------
// Kernel: direct bucket fill. One thread per edge: atomically claim a slot in
// dst's fixed-capacity bucket, store (src, bits(w)).
// ---------------------------------------------------------------------------
__global__ void fill_direct_kernel(const int* __restrict__ ei,
                                   const float* __restrict__ ew, int E)
{
    const int e = blockIdx.x * blockDim.x + threadIdx.x;
    if (e >= E) return;
    const int src = __ldg(ei + e);
    const int dst = __ldg(ei + E + e);
    const float w = __ldg(ew + e);
    const int pos = atomicAdd(&g_cursor[dst], 1);
    if (pos < CAP)
        g_entries[(size_t)dst * CAP + pos] = make_int2(src, __float_as_int(w));
}

// ---------------------------------------------------------------------------
// Kernel: atomic-free aggregation, WARP-PER-NODE. Lane = (entry slot e 0..3,
// channel octet sub 0..7): 4 entries in flight per iteration, no intra-warp
// degree imbalance. Cross-slot combine via shfl_xor(8,16); e==0 lanes do the
// coalesced 256B RMW into out. Lane 0 re-zeroes the cursor (replay invariant).
// ---------------------------------------------------------------------------
__global__ __launch_bounds__(256) void aggregate_kernel(
    float* __restrict__ out, int n_nodes)
{
    const int lane = threadIdx.x & 31;
    const int warp = threadIdx.x >> 5;
    const int n    = blockIdx.x * 8 + warp;
    if (n >= n_nodes) return;           // warp-uniform exit

    const int e   = lane >> 3;          // entry slot 0..3
    const int sub = lane & 7;           // channel octet 0..7

    int cnt = g_cursor[n];
    if (lane == 0) g_cursor[n] = 0;     // reset for next call
    if (cnt > CAP) cnt = CAP;

    const int2* __restrict__ bucket = g_entries + (size_t)n * CAP;

    float acc[8];
#pragma unroll
    for (int c = 0; c < 8; ++c) acc[c] = 0.0f;

    for (int j = 0; j < cnt; j += 4) {
        const int je = j + e;
        // Masked lanes: w = 0, harmless gather of row 0.
        const int2 ent = (je < cnt) ? __ldg(bucket + je) : make_int2(0, 0);
        const float w  = __int_as_float(ent.y);
        const uint4 v  = *reinterpret_cast<const uint4*>(
            g_yh + (size_t)ent.x * HID + sub * 8);
        const unsigned* pv = &v.x;
#pragma unroll
        for (int q = 0; q < 4; ++q) {
            const float2 f = __half22float2(
                *reinterpret_cast<const __half2*>(&pv[q]));
            acc[2*q]   = fmaf(w, f.x, acc[2*q]);
            acc[2*q+1] = fmaf(w, f.y, acc[2*q+1]);
        }
    }

    // Combine entry slots: lanes {e=0..3, same sub} hold partials for the
    // same 8 channels -> butterfly over bits 3 and 4 of the lane id.
#pragma unroll
    for (int c = 0; c < 8; ++c) {
        acc[c] += __shfl_xor_sync(0xffffffffu, acc[c], 8);
        acc[c] += __shfl_xor_sync(0xffffffffu, acc[c], 16);
    }

    if (e == 0) {
        float4* p = reinterpret_cast<float4*>(out + (size_t)n * HID + sub * 8);
        float4 a = p[0], b = p[1];
        a.x += acc[0]; a.y += acc[1]; a.z += acc[2]; a.w += acc[3];
        b.x += acc[4]; b.y += acc[5]; b.z += acc[6]; b.w += acc[7];
        p[0] = a; p[1] = b;
    }
}

// ---------------------------------------------------------------------------
// One-time side-stream/event setup (host objects only — no device memory).
// ---------------------------------------------------------------------------
struct ForkCtx {
    cudaStream_t s2;
    cudaEvent_t  ev_fork, ev_join;
    ForkCtx() {
        cudaStreamCreateWithFlags(&s2, cudaStreamNonBlocking);
        cudaEventCreateWithFlags(&ev_fork, cudaEventDisableTiming);
        cudaEventCreateWithFlags(&ev_join, cudaEventDisableTiming);
    }
};
static ForkCtx& fork_ctx() { static ForkCtx c; return c; }

// ---------------------------------------------------------------------------
extern "C" void kernel_launch(void* const* d_in, const int* in_sizes, int n_in,
                              void* d_out, int out_size)
{
    const float* x      = (const float*)d_in[0];
    const int*   ei     = (const int*)d_in[1];
    const float* ew     = (const float*)d_in[2];
    const float* W_rel  = (const float*)d_in[3];
    const float* b_rel  = (const float*)d_in[4];
    const float* W_root = (const float*)d_in[5];
    float*       out    = (float*)d_out;

    const int n_nodes = in_sizes[0] / IN_CH;
    const int E       = in_sizes[1] / 2;   // edge_index is [2, E] int32

    ForkCtx& fc = fork_ctx();

    // Fork: transform (writes out + g_yh) on side stream.
    cudaEventRecord(fc.ev_fork, 0);
    cudaStreamWaitEvent(fc.s2, fc.ev_fork, 0);
    transform_kernel<<<2048, 64, 0, fc.s2>>>(x, W_rel, b_rel, W_root,
                                             out, n_nodes);
    cudaEventRecord(fc.ev_join, fc.s2);

    // Main stream: single-kernel bucket build (parallel to transform).
    fill_direct_kernel<<<(E + 255) / 256, 256>>>(ei, ew, E);

    // Join, then aggregate: out[n] += sum_{e: dst=n} w_e * y[src_e]
    cudaStreamWaitEvent(0, fc.ev_join, 0);
    aggregate_kernel<<<(n_nodes + 7) / 8, 256>>>(out, n_nodes);
}

// round 13
// speedup vs baseline: 1.9559x; 1.9559x over previous
#include <cuda_runtime.h>
#include <cuda_fp16.h>

#define IN_CH 65
#define HID   64
#define NPAIR 33   // ceil(65/2) packed k-pairs
#define MAX_NODES 100000
#define CAP      128   // bucket capacity per node (deg ~ Poisson(32))

typedef unsigned long long ull;

// ---------------------------------------------------------------------------
// Static scratch (no device-memory allocations allowed).
// g_cursor relies on zero-init for the first call; aggregate_kernel re-zeroes
// it on every execution (replay-safe invariant).
// ---------------------------------------------------------------------------
__device__ __align__(16) __half g_yh[(size_t)MAX_NODES * HID];  // y in fp16
__device__ int  g_cursor[MAX_NODES];                            // bucket fill counts
__device__ int2 g_entries[(size_t)MAX_NODES * CAP];             // (src, bits(w)) buckets

// ---------------------------------------------------------------------------
// Packed f32x2 helpers (Blackwell FFMA2 — only reachable via PTX)
// ---------------------------------------------------------------------------
__device__ __forceinline__ ull pack_f32x2(float lo, float hi) {
    ull r;
    asm("mov.b64 %0, {%1, %2};" : "=l"(r) : "f"(lo), "f"(hi));
    return r;
}
__device__ __forceinline__ void unpack_f32x2(ull v, float& lo, float& hi) {
    asm("mov.b64 {%0, %1}, %2;" : "=f"(lo), "=f"(hi) : "l"(v));
}
__device__ __forceinline__ void fma_f32x2(ull& d, ull a, ull b) {
    asm("fma.rn.f32x2 %0, %1, %2, %0;" : "+l"(d) : "l"(a), "l"(b));
}

// ---------------------------------------------------------------------------
// Kernel: per-node dual matvec (R12-validated: 56.2us, 128 regs).
// 4 nodes/iter, double-buffered smem x, register prefetch; W_rel in regs,
// W_root in smem (conflict-free 8B/lane, reused across the 4 nodes).
//   g_yh[n] = half(W_rel @ x[n]);  out[n] = W_root @ x[n] + b_rel
// ---------------------------------------------------------------------------
__global__ __launch_bounds__(64, 8) void transform_kernel(
    const float* __restrict__ x,
    const float* __restrict__ W_rel,
    const float* __restrict__ b_rel,
    const float* __restrict__ W_root,
    float* __restrict__ out,
    int n_nodes)
{
    const int o = threadIdx.x;  // 0..63 output channel

    ull wrp[NPAIR];
    __shared__ ull wop_s[NPAIR][64];
#pragma unroll
    for (int p = 0; p < NPAIR; ++p) {
        const int k0 = 2 * p, k1 = 2 * p + 1;
        const float r0 = W_rel[o * IN_CH + k0];
        const float r1 = (k1 < IN_CH) ? W_rel[o * IN_CH + k1] : 0.0f;
        const float o0 = W_root[o * IN_CH + k0];
        const float o1 = (k1 < IN_CH) ? W_root[o * IN_CH + k1] : 0.0f;
        wrp[p] = pack_f32x2(r0, r1);
        wop_s[p][o] = pack_f32x2(o0, o1);
    }
    const float bias = b_rel[o];

    __shared__ __align__(16) float sx[2][4][68];
    if (o < 24) {
        const int b = o / 12, nd = (o % 12) / 3, k = 65 + (o % 3);
        sx[b][nd][k] = 0.0f;
    }

    const int total_elems = n_nodes * IN_CH;
    const int stride = gridDim.x * 4;

    int n0 = blockIdx.x * 4;

    {
        const int base = n0 * IN_CH;
#pragma unroll
        for (int j = 0; j < 5; ++j) {
            const int idx = o + j * 64;
            if (idx < 4 * IN_CH && base + idx < total_elems) {
                const int nd = idx / IN_CH;
                const int k  = idx - nd * IN_CH;
                sx[0][nd][k] = x[base + idx];
            }
        }
    }
    __syncthreads();   // covers wop_s + sx buffer 0

    for (int it = 0; n0 < n_nodes; n0 += stride, ++it) {
        const int buf = it & 1;

        const int nn = n0 + stride;
        float pf[5];
#pragma unroll
        for (int j = 0; j < 5; ++j) {
            const int idx = o + j * 64;
            const int gidx = nn * IN_CH + idx;
            pf[j] = (idx < 4 * IN_CH && nn < n_nodes && gidx < total_elems)
                        ? x[gidx] : 0.0f;
        }

        const ull* sp0 = reinterpret_cast<const ull*>(sx[buf][0]);
        const ull* sp1 = reinterpret_cast<const ull*>(sx[buf][1]);
        const ull* sp2 = reinterpret_cast<const ull*>(sx[buf][2]);
        const ull* sp3 = reinterpret_cast<const ull*>(sx[buf][3]);

        ull aY0 = 0, aY1 = 0, aY2 = 0, aY3 = 0;
        ull aO0 = 0, aO1 = 0, aO2 = 0, aO3 = 0;
#pragma unroll
        for (int p = 0; p < NPAIR; ++p) {
            const ull w_r = wrp[p];
            const ull w_o = wop_s[p][o];
            const ull x0 = sp0[p], x1 = sp1[p], x2 = sp2[p], x3 = sp3[p];
            fma_f32x2(aY0, w_r, x0); fma_f32x2(aO0, w_o, x0);
            fma_f32x2(aY1, w_r, x1); fma_f32x2(aO1, w_o, x1);
            fma_f32x2(aY2, w_r, x2); fma_f32x2(aO2, w_o, x2);
            fma_f32x2(aY3, w_r, x3); fma_f32x2(aO3, w_o, x3);
        }

        float lo, hi;
#define STORE_NODE(idx, AY, AO)                                              \
        if (n0 + (idx) < n_nodes) {                                         \
            unpack_f32x2(AY, lo, hi);                                       \
            g_yh[(size_t)(n0 + (idx)) * HID + o] = __float2half(lo + hi);   \
            unpack_f32x2(AO, lo, hi);                                       \
            out[(size_t)(n0 + (idx)) * HID + o] = lo + hi + bias;           \
        }
        STORE_NODE(0, aY0, aO0)
        STORE_NODE(1, aY1, aO1)
        STORE_NODE(2, aY2, aO2)
        STORE_NODE(3, aY3, aO3)
#undef STORE_NODE

#pragma unroll
        for (int j = 0; j < 5; ++j) {
            const int idx = o + j * 64;
            if (idx < 4 * IN_CH) {
                const int nd = idx / IN_CH;
                const int k  = idx - nd * IN_CH;
                sx[buf ^ 1][nd][k] = pf[j];
            }
        }
        __syncthreads();
    }
}

// ---------------------------------------------------------------------------
// Kernel: direct bucket fill. One thread per edge: atomically claim a slot in
// dst's fixed-capacity bucket, store (src, bits(w)).
// ---------------------------------------------------------------------------
__global__ void fill_direct_kernel(const int* __restrict__ ei,
                                   const float* __restrict__ ew, int E)
{
    const int e = blockIdx.x * blockDim.x + threadIdx.x;
    if (e >= E) return;
    const int src = __ldg(ei + e);
    const int dst = __ldg(ei + E + e);
    const float w = __ldg(ew + e);
    const int pos = atomicAdd(&g_cursor[dst], 1);
    if (pos < CAP)
        g_entries[(size_t)dst * CAP + pos] = make_int2(src, __float_as_int(w));
}

// ---------------------------------------------------------------------------
// Kernel: atomic-free aggregation over fp16 y (validated 150.4-baseline
// version). 8-lane group owns one node; each lane covers 8 channels, unroll-2
// entry loop, fp32 accum, one plain RMW into out. Lane 0 re-zeroes the
// node's cursor after reading (replay invariant).
// ---------------------------------------------------------------------------
__global__ __launch_bounds__(256) void aggregate_kernel(
    float* __restrict__ out, int n_nodes)
{
    const int tid = threadIdx.x;
    const int sub = tid & 7;                        // channel octet 0..7
    const int grp = tid >> 3;                       // group slot 0..31
    const int n   = blockIdx.x * 32 + grp;
    if (n >= n_nodes) return;

    int cnt = g_cursor[n];
    if (sub == 0) g_cursor[n] = 0;                  // reset for next call
    if (cnt > CAP) cnt = CAP;

    const int2* __restrict__ bucket = g_entries + (size_t)n * CAP;

    float acc[8];
#pragma unroll
    for (int c = 0; c < 8; ++c) acc[c] = 0.0f;

    int j = 0;
    for (; j + 1 < cnt; j += 2) {
        const int2 e0 = __ldg(bucket + j);
        const int2 e1 = __ldg(bucket + j + 1);
        const float w0 = __int_as_float(e0.y);
        const float w1 = __int_as_float(e1.y);
        const uint4 v0 = *reinterpret_cast<const uint4*>(
            g_yh + (size_t)e0.x * HID + sub * 8);
        const uint4 v1 = *reinterpret_cast<const uint4*>(
            g_yh + (size_t)e1.x * HID + sub * 8);
        const unsigned* p0 = &v0.x;
        const unsigned* p1 = &v1.x;
#pragma unroll
        for (int q = 0; q < 4; ++q) {
            const float2 f0 = __half22float2(
                *reinterpret_cast<const __half2*>(&p0[q]));
            const float2 f1 = __half22float2(
                *reinterpret_cast<const __half2*>(&p1[q]));
            acc[2*q]   = fmaf(w0, f0.x, acc[2*q]);
            acc[2*q+1] = fmaf(w0, f0.y, acc[2*q+1]);
            acc[2*q]   = fmaf(w1, f1.x, acc[2*q]);
            acc[2*q+1] = fmaf(w1, f1.y, acc[2*q+1]);
        }
    }
    if (j < cnt) {
        const int2 e0 = __ldg(bucket + j);
        const float w0 = __int_as_float(e0.y);
        const uint4 v0 = *reinterpret_cast<const uint4*>(
            g_yh + (size_t)e0.x * HID + sub * 8);
        const unsigned* p0 = &v0.x;
#pragma unroll
        for (int q = 0; q < 4; ++q) {
            const float2 f0 = __half22float2(
                *reinterpret_cast<const __half2*>(&p0[q]));
            acc[2*q]   = fmaf(w0, f0.x, acc[2*q]);
            acc[2*q+1] = fmaf(w0, f0.y, acc[2*q+1]);
        }
    }

    float4* p = reinterpret_cast<float4*>(out + (size_t)n * HID + sub * 8);
    float4 a = p[0], b = p[1];
    a.x += acc[0]; a.y += acc[1]; a.z += acc[2]; a.w += acc[3];
    b.x += acc[4]; b.y += acc[5]; b.z += acc[6]; b.w += acc[7];
    p[0] = a; p[1] = b;
}

// ---------------------------------------------------------------------------
// One-time side-stream/event setup (host objects only — no device memory).
// ---------------------------------------------------------------------------
struct ForkCtx {
    cudaStream_t s2;
    cudaEvent_t  ev_fork, ev_join;
    ForkCtx() {
        cudaStreamCreateWithFlags(&s2, cudaStreamNonBlocking);
        cudaEventCreateWithFlags(&ev_fork, cudaEventDisableTiming);
        cudaEventCreateWithFlags(&ev_join, cudaEventDisableTiming);
    }
};
static ForkCtx& fork_ctx() { static ForkCtx c; return c; }

// ---------------------------------------------------------------------------
extern "C" void kernel_launch(void* const* d_in, const int* in_sizes, int n_in,
                              void* d_out, int out_size)
{
    const float* x      = (const float*)d_in[0];
    const int*   ei     = (const int*)d_in[1];
    const float* ew     = (const float*)d_in[2];
    const float* W_rel  = (const float*)d_in[3];
    const float* b_rel  = (const float*)d_in[4];
    const float* W_root = (const float*)d_in[5];
    float*       out    = (float*)d_out;

    const int n_nodes = in_sizes[0] / IN_CH;
    const int E       = in_sizes[1] / 2;   // edge_index is [2, E] int32

    ForkCtx& fc = fork_ctx();

    // Fork: transform (writes out + g_yh) on side stream.
    cudaEventRecord(fc.ev_fork, 0);
    cudaStreamWaitEvent(fc.s2, fc.ev_fork, 0);
    transform_kernel<<<2048, 64, 0, fc.s2>>>(x, W_rel, b_rel, W_root,
                                             out, n_nodes);
    cudaEventRecord(fc.ev_join, fc.s2);

    // Main stream: single-kernel bucket build (parallel to transform).
    fill_direct_kernel<<<(E + 255) / 256, 256>>>(ei, ew, E);

    // Join, then aggregate: out[n] += sum_{e: dst=n} w_e * y[src_e]
    cudaStreamWaitEvent(0, fc.ev_join, 0);
    aggregate_kernel<<<(n_nodes + 31) / 32, 256>>>(out, n_nodes);
}